// round 5
// baseline (speedup 1.0000x reference)
#include <cuda_runtime.h>

typedef unsigned long long u64;

#define TT 50
#define EE 10
#define BB 65536

// Scratch: S[t][b][20] = { x_t[b][0..10), a_t[b][0..10) }, 262 MB device global.
__device__ float g_S[(long)TT * BB * 20];

// ---------------- Pass 1: transpose [B][T][E] -> [T][B][20] ----------------
#define BTILE 32
#define TCH   10

__global__ void __launch_bounds__(256) transpose_kernel(
    const float* __restrict__ X, const float* __restrict__ A)
{
    __shared__ __align__(16) float sX[BTILE][TCH * EE];   // 32 x 100
    __shared__ __align__(16) float sA[BTILE][TCH * EE];

    int b0 = blockIdx.x * BTILE;
    int tcy = blockIdx.y;
    const float4* X4 = (const float4*)X;
    const float4* A4 = (const float4*)A;

    for (int idx = threadIdx.x; idx < BTILE * 25; idx += blockDim.x){
        int r = idx / 25, c = idx % 25;
        long g = (long)(b0 + r) * 125 + (long)tcy * 25 + c;
        float4 v = X4[g];
        *(float4*)&sX[r][4*c] = v;
        float4 w = A4[g];
        *(float4*)&sA[r][4*c] = w;
    }
    __syncthreads();

    float2* S2 = (float2*)g_S;
    for (int idx = threadIdx.x; idx < TCH * BTILE * 10; idx += blockDim.x){
        int e2 = idx % 10;
        int b  = (idx / 10) % BTILE;
        int t  = idx / (10 * BTILE);
        float2 v;
        if (e2 < 5) v = *(const float2*)&sX[b][t*EE + 2*e2];
        else        v = *(const float2*)&sA[b][t*EE + 2*(e2-5)];
        long o = ((long)(tcy*TCH + t) * BB + (b0 + b)) * 10 + e2;
        S2[o] = v;
    }
}

// ---------------- Pass 2: recurrence (2 batches/thread, FFMA2, smem-staged) ----------------
__device__ __forceinline__ u64 ffma2(u64 a, u64 b, u64 c){
    u64 d; asm("fma.rn.f32x2 %0, %1, %2, %3;" : "=l"(d) : "l"(a), "l"(b), "l"(c)); return d;
}
__device__ __forceinline__ u64 splat2(float v){
    u64 r; asm("mov.b64 %0, {%1, %1};" : "=l"(r) : "f"(v)); return r;
}
__device__ __forceinline__ void unpack2(u64 v, float& lo, float& hi){
    asm("mov.b64 {%0, %1}, %2;" : "=f"(lo), "=f"(hi) : "l"(v));
}
__device__ __forceinline__ float sigmoidf_fast(float v){
    return __fdividef(1.0f, 1.0f + __expf(-v));
}
__device__ __forceinline__ float tanhf_fast(float v){
    return 1.0f - __fdividef(2.0f, __expf(2.0f * v) + 1.0f);
}

// Load one padded weight row (10 floats) once; apply to both batches' acc pairs.
__device__ __forceinline__ void mac2(u64* __restrict__ a0, u64* __restrict__ a1,
                                     const float* __restrict__ row, u64 s0, u64 s1){
    ulonglong2 w01 = *(const ulonglong2*)row;        // pairs (0,1),(2,3)
    ulonglong2 w23 = *(const ulonglong2*)(row + 4);  // pairs (4,5),(6,7)
    u64 w4 = *(const u64*)(row + 8);                 // pair (8,9)
    a0[0] = ffma2(s0, w01.x, a0[0]);  a1[0] = ffma2(s1, w01.x, a1[0]);
    a0[1] = ffma2(s0, w01.y, a0[1]);  a1[1] = ffma2(s1, w01.y, a1[1]);
    a0[2] = ffma2(s0, w23.x, a0[2]);  a1[2] = ffma2(s1, w23.x, a1[2]);
    a0[3] = ffma2(s0, w23.y, a0[3]);  a1[3] = ffma2(s1, w23.y, a1[3]);
    a0[4] = ffma2(s0, w4,    a0[4]);  a1[4] = ffma2(s1, w4,    a1[4]);
}

#define NTH 128         // threads per CTA
#define BPT 2           // batches per thread
#define NB  (NTH*BPT)   // 256 batches per CTA
#define RSTRIDE 22      // padded row stride in staging buffer

__global__ void __launch_bounds__(NTH) augru_kernel(
    const float* __restrict__ h0,
    const float* __restrict__ Wi_r, const float* __restrict__ bi_r,
    const float* __restrict__ Wh_r, const float* __restrict__ Ws_r, const float* __restrict__ bs_r,
    const float* __restrict__ Wi_z, const float* __restrict__ bi_z,
    const float* __restrict__ Wh_z, const float* __restrict__ Ws_z, const float* __restrict__ bs_z,
    const float* __restrict__ Wi_h, const float* __restrict__ bi_h,
    const float* __restrict__ Wh_h, const float* __restrict__ Wt_h, const float* __restrict__ bt_h,
    float* __restrict__ out)
{
    // Fused: sW[0]=Wi_r@Ws_r, sW[1]=Wh_r@Ws_r, sW[2]=Wi_z@Ws_z,
    //        sW[3]=Wh_z@Ws_z, sW[4]=Wi_h@Wt_h, sW[5]=Wh_h@Wt_h. Rows padded to 16 floats.
    __shared__ __align__(16) float sW[6][160];
    __shared__ __align__(16) float sB[3][16];
    __shared__ float sH0[16];
    __shared__ __align__(16) float sIn[2][NB * RSTRIDE];   // 2 x 22528 B

    {
        const float* W1[6] = {Wi_r, Wh_r, Wi_z, Wh_z, Wi_h, Wh_h};
        const float* W2[6] = {Ws_r, Ws_r, Ws_z, Ws_z, Wt_h, Wt_h};
        for (int idx = threadIdx.x; idx < 6 * 160; idx += NTH){
            int m = idx / 160, r = idx % 160, i = r >> 4, j = r & 15;
            float v = 0.0f;
            if (j < EE){
                const float* a = W1[m]; const float* b2 = W2[m];
                #pragma unroll
                for (int k = 0; k < EE; k++) v = fmaf(a[i*EE + k], b2[k*EE + j], v);
            }
            sW[m][r] = v;
        }
        for (int idx = threadIdx.x; idx < 48; idx += NTH){
            int g = idx >> 4, j = idx & 15;
            float v = 0.0f;
            if (j < EE){
                const float* bi = (g==0) ? bi_r : (g==1) ? bi_z : bi_h;
                const float* bs = (g==0) ? bs_r : (g==1) ? bs_z : bt_h;
                const float* Wg = (g==0) ? Ws_r : (g==1) ? Ws_z : Wt_h;
                v = bs[j];
                #pragma unroll
                for (int k = 0; k < EE; k++) v = fmaf(bi[k], Wg[k*EE + j], v);
            }
            sB[g][j] = v;
        }
        if (threadIdx.x < 16) sH0[threadIdx.x] = (threadIdx.x < EE) ? h0[threadIdx.x] : 0.0f;
    }

    const int tid = threadIdx.x;
    const int b0  = blockIdx.x * NB;

    // Cooperative slab load: NB batches x 20 floats = 1280 float4; 10 per thread.
    const float4* Sbase = (const float4*)(g_S + (long)b0 * 20);

    float4 f4[10];
    #pragma unroll
    for (int k = 0; k < 10; k++) f4[k] = Sbase[tid + NTH*k];   // t = 0

    #pragma unroll
    for (int k = 0; k < 10; k++){
        int e = 4*(tid + NTH*k);
        int row = e / 20, col = e % 20;
        float* d = &sIn[0][row * RSTRIDE + col];
        *(float2*)(d)     = make_float2(f4[k].x, f4[k].y);
        *(float2*)(d + 2) = make_float2(f4[k].z, f4[k].w);
    }
    __syncthreads();

    float h[BPT][EE];
    #pragma unroll
    for (int bb = 0; bb < BPT; bb++)
        #pragma unroll
        for (int j = 0; j < EE; j++) h[bb][j] = sH0[j];

    #pragma unroll 1
    for (int t = 0; t < TT; t++){
        // prefetch slab t+1
        if (t + 1 < TT){
            const float4* Sn = (const float4*)(g_S + ((long)(t+1) * BB + b0) * 20);
            #pragma unroll
            for (int k = 0; k < 10; k++) f4[k] = Sn[tid + NTH*k];
        }

        // ---- load x for both batches from sIn[t&1] ----
        const float* my0 = &sIn[t & 1][tid * RSTRIDE];
        const float* my1 = &sIn[t & 1][(tid + NTH) * RSTRIDE];
        float x[BPT][EE];
        #pragma unroll
        for (int p = 0; p < 5; p++){
            float2 v0 = *(const float2*)(my0 + 2*p);
            x[0][2*p] = v0.x; x[0][2*p+1] = v0.y;
            float2 v1 = *(const float2*)(my1 + 2*p);
            x[1][2*p] = v1.x; x[1][2*p+1] = v1.y;
        }

        u64 accR[BPT][5], accZ[BPT][5], accH[BPT][5];
        #pragma unroll
        for (int bb = 0; bb < BPT; bb++)
            #pragma unroll
            for (int p = 0; p < 5; p++){
                accR[bb][p] = *(const u64*)&sB[0][2*p];
                accZ[bb][p] = *(const u64*)&sB[1][2*p];
                accH[bb][p] = *(const u64*)&sB[2][2*p];
            }

        // x contributions (weight rows loaded once, applied to both batches)
        #pragma unroll
        for (int i = 0; i < EE; i++){
            u64 s0 = splat2(x[0][i]), s1 = splat2(x[1][i]);
            mac2(accR[0], accR[1], &sW[0][i*16], s0, s1);
            mac2(accZ[0], accZ[1], &sW[2][i*16], s0, s1);
            mac2(accH[0], accH[1], &sW[4][i*16], s0, s1);
        }
        // h contributions
        #pragma unroll
        for (int i = 0; i < EE; i++){
            u64 s0 = splat2(h[0][i]), s1 = splat2(h[1][i]);
            mac2(accR[0], accR[1], &sW[1][i*16], s0, s1);
            mac2(accZ[0], accZ[1], &sW[3][i*16], s0, s1);
        }

        float r[BPT][EE], g[BPT][EE];
        #pragma unroll
        for (int bb = 0; bb < BPT; bb++)
            #pragma unroll
            for (int p = 0; p < 5; p++){
                float r0, r1; unpack2(accR[bb][p], r0, r1);
                r[bb][2*p]   = sigmoidf_fast(r0);
                r[bb][2*p+1] = sigmoidf_fast(r1);
                float z0, z1; unpack2(accZ[bb][p], z0, z1);
                g[bb][2*p]   = h[bb][2*p]   * sigmoidf_fast(z0);
                g[bb][2*p+1] = h[bb][2*p+1] * sigmoidf_fast(z1);
            }

        // (h*z) contribution to candidate
        #pragma unroll
        for (int i = 0; i < EE; i++){
            u64 s0 = splat2(g[0][i]), s1 = splat2(g[1][i]);
            mac2(accH[0], accH[1], &sW[5][i*16], s0, s1);
        }

        // final combine; a loaded just-in-time to shorten live ranges
        #pragma unroll
        for (int bb = 0; bb < BPT; bb++){
            const float* my = (bb == 0) ? my0 : my1;
            #pragma unroll
            for (int p = 0; p < 5; p++){
                float c0, c1; unpack2(accH[bb][p], c0, c1);
                float hc0 = tanhf_fast(c0);
                float hc1 = tanhf_fast(c1);
                float2 av = *(const float2*)(my + 10 + 2*p);
                float Ra0 = av.x * r[bb][2*p];
                float Ra1 = av.y * r[bb][2*p+1];
                h[bb][2*p]   = h[bb][2*p]   + Ra0 * (hc0 - h[bb][2*p]);
                h[bb][2*p+1] = h[bb][2*p+1] + Ra1 * (hc1 - h[bb][2*p+1]);
            }
        }

        // stage slab t+1
        if (t + 1 < TT){
            float* buf = sIn[(t + 1) & 1];
            #pragma unroll
            for (int k = 0; k < 10; k++){
                int e = 4*(tid + NTH*k);
                int row = e / 20, col = e % 20;
                float* d = &buf[row * RSTRIDE + col];
                *(float2*)(d)     = make_float2(f4[k].x, f4[k].y);
                *(float2*)(d + 2) = make_float2(f4[k].z, f4[k].w);
            }
        }
        __syncthreads();
    }

    #pragma unroll
    for (int bb = 0; bb < BPT; bb++){
        long b = (long)b0 + tid + bb * NTH;
        #pragma unroll
        for (int p = 0; p < 5; p++){
            float2 o; o.x = h[bb][2*p]; o.y = h[bb][2*p+1];
            *(float2*)(out + b*EE + 2*p) = o;
        }
    }
}

extern "C" void kernel_launch(void* const* d_in, const int* in_sizes, int n_in,
                              void* d_out, int out_size)
{
    const float* X   = (const float*)d_in[0];
    const float* Aat = (const float*)d_in[1];
    const float* h0  = (const float*)d_in[2];

    dim3 tg(BB / BTILE, TT / TCH);      // 2048 x 5
    transpose_kernel<<<tg, 256>>>(X, Aat);

    augru_kernel<<<BB / NB, NTH>>>(
        h0,
        (const float*)d_in[3],  (const float*)d_in[4],  (const float*)d_in[5],
        (const float*)d_in[6],  (const float*)d_in[7],
        (const float*)d_in[8],  (const float*)d_in[9],  (const float*)d_in[10],
        (const float*)d_in[11], (const float*)d_in[12],
        (const float*)d_in[13], (const float*)d_in[14], (const float*)d_in[15],
        (const float*)d_in[16], (const float*)d_in[17],
        (float*)d_out);
}

// round 7
// speedup vs baseline: 1.2458x; 1.2458x over previous
#include <cuda_runtime.h>

typedef unsigned long long u64;

#define TT 50
#define EE 10
#define BB 65536

// Scratch: S[t][b][20] = { x_t[b][0..10), a_t[b][0..10) }, 262 MB device global.
__device__ float g_S[(long)TT * BB * 20];

// ---------------- Pass 1: transpose [B][T][E] -> [T][B][20] ----------------
#define BTILE 32
#define TCH   10

__global__ void __launch_bounds__(256) transpose_kernel(
    const float* __restrict__ X, const float* __restrict__ A)
{
    __shared__ __align__(16) float sX[BTILE][TCH * EE];   // 32 x 100
    __shared__ __align__(16) float sA[BTILE][TCH * EE];

    int b0 = blockIdx.x * BTILE;
    int tcy = blockIdx.y;
    const float4* X4 = (const float4*)X;
    const float4* A4 = (const float4*)A;

    for (int idx = threadIdx.x; idx < BTILE * 25; idx += blockDim.x){
        int r = idx / 25, c = idx % 25;
        long g = (long)(b0 + r) * 125 + (long)tcy * 25 + c;
        float4 v = X4[g];
        *(float4*)&sX[r][4*c] = v;
        float4 w = A4[g];
        *(float4*)&sA[r][4*c] = w;
    }
    __syncthreads();

    float2* S2 = (float2*)g_S;
    for (int idx = threadIdx.x; idx < TCH * BTILE * 10; idx += blockDim.x){
        int e2 = idx % 10;
        int b  = (idx / 10) % BTILE;
        int t  = idx / (10 * BTILE);
        float2 v;
        if (e2 < 5) v = *(const float2*)&sX[b][t*EE + 2*e2];
        else        v = *(const float2*)&sA[b][t*EE + 2*(e2-5)];
        long o = ((long)(tcy*TCH + t) * BB + (b0 + b)) * 10 + e2;
        S2[o] = v;
    }
}

// ---------------- Pass 2: recurrence (256 thr, 1 batch/thread, FFMA2, smem-staged) ----------------
__device__ __forceinline__ u64 ffma2(u64 a, u64 b, u64 c){
    u64 d; asm("fma.rn.f32x2 %0, %1, %2, %3;" : "=l"(d) : "l"(a), "l"(b), "l"(c)); return d;
}
__device__ __forceinline__ u64 splat2(float v){
    u64 r; asm("mov.b64 %0, {%1, %1};" : "=l"(r) : "f"(v)); return r;
}
__device__ __forceinline__ void unpack2(u64 v, float& lo, float& hi){
    asm("mov.b64 {%0, %1}, %2;" : "=f"(lo), "=f"(hi) : "l"(v));
}
__device__ __forceinline__ float sigmoidf_fast(float v){
    return __fdividef(1.0f, 1.0f + __expf(-v));
}
__device__ __forceinline__ float tanhf_fast(float v){
    return 1.0f - __fdividef(2.0f, __expf(2.0f * v) + 1.0f);
}

__device__ __forceinline__ void mac_row(u64* __restrict__ acc, const float* __restrict__ row, u64 s){
    ulonglong2 w01 = *(const ulonglong2*)row;        // pairs (0,1),(2,3)
    ulonglong2 w23 = *(const ulonglong2*)(row + 4);  // pairs (4,5),(6,7)
    u64 w4 = *(const u64*)(row + 8);                 // pair (8,9)
    acc[0] = ffma2(s, w01.x, acc[0]);
    acc[1] = ffma2(s, w01.y, acc[1]);
    acc[2] = ffma2(s, w23.x, acc[2]);
    acc[3] = ffma2(s, w23.y, acc[3]);
    acc[4] = ffma2(s, w4,    acc[4]);
}

#define NTH 256
#define RSTRIDE 22   // padded row stride (floats) in staging buffer

__global__ void __launch_bounds__(NTH, 2) augru_kernel(
    const float* __restrict__ h0,
    const float* __restrict__ Wi_r, const float* __restrict__ bi_r,
    const float* __restrict__ Wh_r, const float* __restrict__ Ws_r, const float* __restrict__ bs_r,
    const float* __restrict__ Wi_z, const float* __restrict__ bi_z,
    const float* __restrict__ Wh_z, const float* __restrict__ Ws_z, const float* __restrict__ bs_z,
    const float* __restrict__ Wi_h, const float* __restrict__ bi_h,
    const float* __restrict__ Wh_h, const float* __restrict__ Wt_h, const float* __restrict__ bt_h,
    float* __restrict__ out)
{
    // Fused: sW[0]=Wi_r@Ws_r, sW[1]=Wh_r@Ws_r, sW[2]=Wi_z@Ws_z,
    //        sW[3]=Wh_z@Ws_z, sW[4]=Wi_h@Wt_h, sW[5]=Wh_h@Wt_h. Rows padded to 16 floats.
    __shared__ __align__(16) float sW[6][160];
    __shared__ __align__(16) float sB[3][16];
    __shared__ float sH0[16];
    __shared__ __align__(16) float sIn[2][NTH * RSTRIDE];   // 2 x 22528 B

    {
        const float* W1[6] = {Wi_r, Wh_r, Wi_z, Wh_z, Wi_h, Wh_h};
        const float* W2[6] = {Ws_r, Ws_r, Ws_z, Ws_z, Wt_h, Wt_h};
        for (int idx = threadIdx.x; idx < 6 * 160; idx += NTH){
            int m = idx / 160, r = idx % 160, i = r >> 4, j = r & 15;
            float v = 0.0f;
            if (j < EE){
                const float* a = W1[m]; const float* b2 = W2[m];
                #pragma unroll
                for (int k = 0; k < EE; k++) v = fmaf(a[i*EE + k], b2[k*EE + j], v);
            }
            sW[m][r] = v;
        }
        for (int idx = threadIdx.x; idx < 48; idx += NTH){
            int g = idx >> 4, j = idx & 15;
            float v = 0.0f;
            if (j < EE){
                const float* bi = (g==0) ? bi_r : (g==1) ? bi_z : bi_h;
                const float* bs = (g==0) ? bs_r : (g==1) ? bs_z : bt_h;
                const float* Wg = (g==0) ? Ws_r : (g==1) ? Ws_z : Wt_h;
                v = bs[j];
                #pragma unroll
                for (int k = 0; k < EE; k++) v = fmaf(bi[k], Wg[k*EE + j], v);
            }
            sB[g][j] = v;
        }
        if (threadIdx.x < 16) sH0[threadIdx.x] = (threadIdx.x < EE) ? h0[threadIdx.x] : 0.0f;
    }

    const int tid = threadIdx.x;
    const int b0  = blockIdx.x * NTH;

    // Cooperative slab load: 256 batches x 20 floats = 1280 float4; 5 per thread.
    const float4* Sbase = (const float4*)(g_S + (long)b0 * 20);

    float4 f4[5];
    #pragma unroll
    for (int k = 0; k < 5; k++) f4[k] = Sbase[tid + NTH*k];   // t = 0

    #pragma unroll
    for (int k = 0; k < 5; k++){
        int e = 4*(tid + NTH*k);
        int row = e / 20, col = e % 20;
        float* d = &sIn[0][row * RSTRIDE + col];
        *(float2*)(d)     = make_float2(f4[k].x, f4[k].y);
        *(float2*)(d + 2) = make_float2(f4[k].z, f4[k].w);
    }
    __syncthreads();

    float h[EE];
    #pragma unroll
    for (int j = 0; j < EE; j++) h[j] = sH0[j];

    #pragma unroll 1
    for (int t = 0; t < TT; t++){
        // prefetch slab t+1 (consumed at loop bottom)
        if (t + 1 < TT){
            const float4* Sn = (const float4*)(g_S + ((long)(t+1) * BB + b0) * 20);
            #pragma unroll
            for (int k = 0; k < 5; k++) f4[k] = Sn[tid + NTH*k];
        }

        // ---- load x from staged slab ----
        const float* my = &sIn[t & 1][tid * RSTRIDE];
        float x[EE];
        #pragma unroll
        for (int p = 0; p < 5; p++){
            float2 v = *(const float2*)(my + 2*p);
            x[2*p] = v.x; x[2*p+1] = v.y;
        }

        u64 accR[5], accZ[5], accH[5];
        #pragma unroll
        for (int p = 0; p < 5; p++){
            accR[p] = *(const u64*)&sB[0][2*p];
            accZ[p] = *(const u64*)&sB[1][2*p];
            accH[p] = *(const u64*)&sB[2][2*p];
        }

        // x contributions to all three gates (splat shared across 3 rows)
        #pragma unroll
        for (int i = 0; i < EE; i++){
            u64 sx = splat2(x[i]);
            mac_row(accR, &sW[0][i*16], sx);
            mac_row(accZ, &sW[2][i*16], sx);
            mac_row(accH, &sW[4][i*16], sx);
        }
        // h contributions to r and z
        #pragma unroll
        for (int i = 0; i < EE; i++){
            u64 sh = splat2(h[i]);
            mac_row(accR, &sW[1][i*16], sh);
            mac_row(accZ, &sW[3][i*16], sh);
        }

        float r[EE], g[EE];
        #pragma unroll
        for (int p = 0; p < 5; p++){
            float r0, r1; unpack2(accR[p], r0, r1);
            r[2*p]   = sigmoidf_fast(r0);
            r[2*p+1] = sigmoidf_fast(r1);
            float z0, z1; unpack2(accZ[p], z0, z1);
            g[2*p]   = h[2*p]   * sigmoidf_fast(z0);
            g[2*p+1] = h[2*p+1] * sigmoidf_fast(z1);
        }

        // (h*z) contribution to candidate
        #pragma unroll
        for (int i = 0; i < EE; i++){
            u64 sg = splat2(g[i]);
            mac_row(accH, &sW[5][i*16], sg);
        }

        // final combine; a loaded just-in-time from smem
        #pragma unroll
        for (int p = 0; p < 5; p++){
            float c0, c1; unpack2(accH[p], c0, c1);
            float hc0 = tanhf_fast(c0);
            float hc1 = tanhf_fast(c1);
            float2 av = *(const float2*)(my + 10 + 2*p);
            float Ra0 = av.x * r[2*p];
            float Ra1 = av.y * r[2*p+1];
            h[2*p]   = h[2*p]   + Ra0 * (hc0 - h[2*p]);
            h[2*p+1] = h[2*p+1] + Ra1 * (hc1 - h[2*p+1]);
        }

        // stage slab t+1 into the other buffer
        if (t + 1 < TT){
            float* buf = sIn[(t + 1) & 1];
            #pragma unroll
            for (int k = 0; k < 5; k++){
                int e = 4*(tid + NTH*k);
                int row = e / 20, col = e % 20;
                float* d = &buf[row * RSTRIDE + col];
                *(float2*)(d)     = make_float2(f4[k].x, f4[k].y);
                *(float2*)(d + 2) = make_float2(f4[k].z, f4[k].w);
            }
        }
        __syncthreads();
    }

    long b = (long)b0 + tid;
    #pragma unroll
    for (int p = 0; p < 5; p++){
        float2 o; o.x = h[2*p]; o.y = h[2*p+1];
        *(float2*)(out + b*EE + 2*p) = o;
    }
}

extern "C" void kernel_launch(void* const* d_in, const int* in_sizes, int n_in,
                              void* d_out, int out_size)
{
    const float* X   = (const float*)d_in[0];
    const float* Aat = (const float*)d_in[1];
    const float* h0  = (const float*)d_in[2];

    dim3 tg(BB / BTILE, TT / TCH);      // 2048 x 5
    transpose_kernel<<<tg, 256>>>(X, Aat);

    augru_kernel<<<BB / NTH, NTH>>>(
        h0,
        (const float*)d_in[3],  (const float*)d_in[4],  (const float*)d_in[5],
        (const float*)d_in[6],  (const float*)d_in[7],
        (const float*)d_in[8],  (const float*)d_in[9],  (const float*)d_in[10],
        (const float*)d_in[11], (const float*)d_in[12],
        (const float*)d_in[13], (const float*)d_in[14], (const float*)d_in[15],
        (const float*)d_in[16], (const float*)d_in[17],
        (float*)d_out);
}

// round 10
// speedup vs baseline: 1.5605x; 1.2526x over previous
#include <cuda_runtime.h>

typedef unsigned long long u64;

#define TT 50
#define EE 10
#define BB 65536

__device__ __forceinline__ u64 ffma2(u64 a, u64 b, u64 c){
    u64 d; asm("fma.rn.f32x2 %0, %1, %2, %3;" : "=l"(d) : "l"(a), "l"(b), "l"(c)); return d;
}
__device__ __forceinline__ u64 splat2(float v){
    u64 r; asm("mov.b64 %0, {%1, %1};" : "=l"(r) : "f"(v)); return r;
}
__device__ __forceinline__ void unpack2(u64 v, float& lo, float& hi){
    asm("mov.b64 {%0, %1}, %2;" : "=f"(lo), "=f"(hi) : "l"(v));
}
__device__ __forceinline__ float sigmoidf_fast(float v){
    return __fdividef(1.0f, 1.0f + __expf(-v));
}
__device__ __forceinline__ float tanhf_fast(float v){
    return 1.0f - __fdividef(2.0f, __expf(2.0f * v) + 1.0f);
}

__device__ __forceinline__ void mac_row(u64* __restrict__ acc, const float* __restrict__ row, u64 s){
    ulonglong2 w01 = *(const ulonglong2*)row;        // pairs (0,1),(2,3)
    ulonglong2 w23 = *(const ulonglong2*)(row + 4);  // pairs (4,5),(6,7)
    u64 w4 = *(const u64*)(row + 8);                 // pair (8,9)
    acc[0] = ffma2(s, w01.x, acc[0]);
    acc[1] = ffma2(s, w01.y, acc[1]);
    acc[2] = ffma2(s, w23.x, acc[2]);
    acc[3] = ffma2(s, w23.y, acc[3]);
    acc[4] = ffma2(s, w4,    acc[4]);
}

#define NTH 256
#define RSTRIDE 22   // padded row stride (floats) in staging buffer

__global__ void __launch_bounds__(NTH, 2) augru_kernel(
    const float* __restrict__ X, const float* __restrict__ Aat,
    const float* __restrict__ h0,
    const float* __restrict__ Wi_r, const float* __restrict__ bi_r,
    const float* __restrict__ Wh_r, const float* __restrict__ Ws_r, const float* __restrict__ bs_r,
    const float* __restrict__ Wi_z, const float* __restrict__ bi_z,
    const float* __restrict__ Wh_z, const float* __restrict__ Ws_z, const float* __restrict__ bs_z,
    const float* __restrict__ Wi_h, const float* __restrict__ bi_h,
    const float* __restrict__ Wh_h, const float* __restrict__ Wt_h, const float* __restrict__ bt_h,
    float* __restrict__ out)
{
    // Fused: sW[0]=Wi_r@Ws_r, sW[1]=Wh_r@Ws_r, sW[2]=Wi_z@Ws_z,
    //        sW[3]=Wh_z@Ws_z, sW[4]=Wi_h@Wt_h, sW[5]=Wh_h@Wt_h. Rows padded to 16 floats.
    __shared__ __align__(16) float sW[6][160];
    __shared__ __align__(16) float sB[3][16];
    __shared__ float sH0[16];
    __shared__ __align__(16) float sIn[2][NTH * RSTRIDE];   // 2 x 22528 B

    {
        const float* W1[6] = {Wi_r, Wh_r, Wi_z, Wh_z, Wi_h, Wh_h};
        const float* W2[6] = {Ws_r, Ws_r, Ws_z, Ws_z, Wt_h, Wt_h};
        for (int idx = threadIdx.x; idx < 6 * 160; idx += NTH){
            int m = idx / 160, r = idx % 160, i = r >> 4, j = r & 15;
            float v = 0.0f;
            if (j < EE){
                const float* a = W1[m]; const float* b2 = W2[m];
                #pragma unroll
                for (int k = 0; k < EE; k++) v = fmaf(a[i*EE + k], b2[k*EE + j], v);
            }
            sW[m][r] = v;
        }
        for (int idx = threadIdx.x; idx < 48; idx += NTH){
            int g = idx >> 4, j = idx & 15;
            float v = 0.0f;
            if (j < EE){
                const float* bi = (g==0) ? bi_r : (g==1) ? bi_z : bi_h;
                const float* bs = (g==0) ? bs_r : (g==1) ? bs_z : bt_h;
                const float* Wg = (g==0) ? Ws_r : (g==1) ? Ws_z : Wt_h;
                v = bs[j];
                #pragma unroll
                for (int k = 0; k < EE; k++) v = fmaf(bi[k], Wg[k*EE + j], v);
            }
            sB[g][j] = v;
        }
        if (threadIdx.x < 16) sH0[threadIdx.x] = (threadIdx.x < EE) ? h0[threadIdx.x] : 0.0f;
    }

    const int tid = threadIdx.x;
    const long b0 = (long)blockIdx.x * NTH;

    // Cooperative staging directly from the ORIGINAL [B][T][E] layout.
    // Per step the CTA needs 256 batches x 5 float2 (x) + 5 float2 (a).
    // Slot k of this thread: linear idx = tid + 256*k -> (batch bb = idx/5, part pp = idx%5).
    // Global float offset for step t: (b0+bb)*500 + t*10 + pp*2.
    // A warp's 32 lanes cover ~6.4 consecutive batches' 40B chunks; the fetched
    // 128B lines contain t..t+2 of the same batches and are re-hit on later steps (L1-resident).
    long goff[5]; int soff[5];
    #pragma unroll
    for (int k = 0; k < 5; k++){
        int idx = tid + NTH*k;
        int bb = idx / 5, pp = idx % 5;
        goff[k] = (b0 + bb) * (long)(TT*EE) + pp*2;
        soff[k] = bb * RSTRIDE + pp*2;
    }

    float2 fx[5], fa[5];
    #pragma unroll
    for (int k = 0; k < 5; k++){
        fx[k] = *(const float2*)(X   + goff[k]);
        fa[k] = *(const float2*)(Aat + goff[k]);
    }
    #pragma unroll
    for (int k = 0; k < 5; k++){
        *(float2*)&sIn[0][soff[k]]      = fx[k];
        *(float2*)&sIn[0][soff[k] + 10] = fa[k];
    }
    __syncthreads();

    float h[EE];
    #pragma unroll
    for (int j = 0; j < EE; j++) h[j] = sH0[j];

    #pragma unroll 1
    for (int t = 0; t < TT; t++){
        // prefetch step t+1 directly from X/A (consumed at loop bottom)
        if (t + 1 < TT){
            #pragma unroll
            for (int k = 0; k < 5; k++){
                fx[k] = *(const float2*)(X   + goff[k] + (t+1)*EE);
                fa[k] = *(const float2*)(Aat + goff[k] + (t+1)*EE);
            }
        }

        // ---- compute step t from staged slab (identical to proven core) ----
        const float* my = &sIn[t & 1][tid * RSTRIDE];
        float x[EE];
        #pragma unroll
        for (int p = 0; p < 5; p++){
            float2 v = *(const float2*)(my + 2*p);
            x[2*p] = v.x; x[2*p+1] = v.y;
        }

        u64 accR[5], accZ[5], accH[5];
        #pragma unroll
        for (int p = 0; p < 5; p++){
            accR[p] = *(const u64*)&sB[0][2*p];
            accZ[p] = *(const u64*)&sB[1][2*p];
            accH[p] = *(const u64*)&sB[2][2*p];
        }

        #pragma unroll
        for (int i = 0; i < EE; i++){
            u64 sx = splat2(x[i]);
            mac_row(accR, &sW[0][i*16], sx);
            mac_row(accZ, &sW[2][i*16], sx);
            mac_row(accH, &sW[4][i*16], sx);
        }
        #pragma unroll
        for (int i = 0; i < EE; i++){
            u64 sh = splat2(h[i]);
            mac_row(accR, &sW[1][i*16], sh);
            mac_row(accZ, &sW[3][i*16], sh);
        }

        float r[EE], g[EE];
        #pragma unroll
        for (int p = 0; p < 5; p++){
            float r0, r1; unpack2(accR[p], r0, r1);
            r[2*p]   = sigmoidf_fast(r0);
            r[2*p+1] = sigmoidf_fast(r1);
            float z0, z1; unpack2(accZ[p], z0, z1);
            g[2*p]   = h[2*p]   * sigmoidf_fast(z0);
            g[2*p+1] = h[2*p+1] * sigmoidf_fast(z1);
        }

        #pragma unroll
        for (int i = 0; i < EE; i++){
            u64 sg = splat2(g[i]);
            mac_row(accH, &sW[5][i*16], sg);
        }

        #pragma unroll
        for (int p = 0; p < 5; p++){
            float c0, c1; unpack2(accH[p], c0, c1);
            float hc0 = tanhf_fast(c0);
            float hc1 = tanhf_fast(c1);
            float2 av = *(const float2*)(my + 10 + 2*p);
            float Ra0 = av.x * r[2*p];
            float Ra1 = av.y * r[2*p+1];
            h[2*p]   = h[2*p]   + Ra0 * (hc0 - h[2*p]);
            h[2*p+1] = h[2*p+1] + Ra1 * (hc1 - h[2*p+1]);
        }

        // stage step t+1 into the other buffer
        if (t + 1 < TT){
            float* buf = sIn[(t + 1) & 1];
            #pragma unroll
            for (int k = 0; k < 5; k++){
                *(float2*)&buf[soff[k]]      = fx[k];
                *(float2*)&buf[soff[k] + 10] = fa[k];
            }
        }
        __syncthreads();
    }

    long b = b0 + tid;
    #pragma unroll
    for (int p = 0; p < 5; p++){
        float2 o; o.x = h[2*p]; o.y = h[2*p+1];
        *(float2*)(out + b*EE + 2*p) = o;
    }
}

extern "C" void kernel_launch(void* const* d_in, const int* in_sizes, int n_in,
                              void* d_out, int out_size)
{
    const float* X   = (const float*)d_in[0];
    const float* Aat = (const float*)d_in[1];
    const float* h0  = (const float*)d_in[2];

    augru_kernel<<<BB / NTH, NTH>>>(
        X, Aat, h0,
        (const float*)d_in[3],  (const float*)d_in[4],  (const float*)d_in[5],
        (const float*)d_in[6],  (const float*)d_in[7],
        (const float*)d_in[8],  (const float*)d_in[9],  (const float*)d_in[10],
        (const float*)d_in[11], (const float*)d_in[12],
        (const float*)d_in[13], (const float*)d_in[14], (const float*)d_in[15],
        (const float*)d_in[16], (const float*)d_in[17],
        (float*)d_out);
}

// round 12
// speedup vs baseline: 1.9259x; 1.2341x over previous
#include <cuda_runtime.h>

typedef unsigned long long u64;

#define TT 50
#define EE 10
#define BB 65536

__device__ __forceinline__ u64 ffma2(u64 a, u64 b, u64 c){
    u64 d; asm("fma.rn.f32x2 %0, %1, %2, %3;" : "=l"(d) : "l"(a), "l"(b), "l"(c)); return d;
}
__device__ __forceinline__ u64 splat2(float v){
    u64 r; asm("mov.b64 %0, {%1, %1};" : "=l"(r) : "f"(v)); return r;
}
__device__ __forceinline__ void unpack2(u64 v, float& lo, float& hi){
    asm("mov.b64 {%0, %1}, %2;" : "=f"(lo), "=f"(hi) : "l"(v));
}
__device__ __forceinline__ float sigmoidf_fast(float v){
    return __fdividef(1.0f, 1.0f + __expf(-v));
}
__device__ __forceinline__ float tanhf_fast(float v){
    return 1.0f - __fdividef(2.0f, __expf(2.0f * v) + 1.0f);
}

#define NTH 64
#define RSTRIDE 22   // padded row stride (floats) in staging buffer

__global__ void __launch_bounds__(NTH, 7) augru_kernel(
    const float* __restrict__ X, const float* __restrict__ Aat,
    const float* __restrict__ h0,
    const float* __restrict__ Wi_r, const float* __restrict__ bi_r,
    const float* __restrict__ Wh_r, const float* __restrict__ Ws_r, const float* __restrict__ bs_r,
    const float* __restrict__ Wi_z, const float* __restrict__ bi_z,
    const float* __restrict__ Wh_z, const float* __restrict__ Ws_z, const float* __restrict__ bs_z,
    const float* __restrict__ Wi_h, const float* __restrict__ bi_h,
    const float* __restrict__ Wh_h, const float* __restrict__ Wt_h, const float* __restrict__ bt_h,
    float* __restrict__ out)
{
    // Packed fused weights (co-consumed rows contiguous -> fewer LDS):
    //  sWX[i][0..9]=(Wi_r@Ws_r) row i, [10..19]=(Wi_z@Ws_z) row i, [20..29]=(Wi_h@Wt_h) row i, [30..31]=pad
    //  sWH[i][0..9]=(Wh_r@Ws_r) row i, [10..19]=(Wh_z@Ws_z) row i, [20..23]=pad
    //  sWG[i][0..9]=(Wh_h@Wt_h) row i, [10..15]=pad
    __shared__ __align__(16) float sWX[EE][32];
    __shared__ __align__(16) float sWH[EE][24];
    __shared__ __align__(16) float sWG[EE][16];
    __shared__ __align__(16) float sB[3][16];
    __shared__ float sH0[16];
    __shared__ __align__(16) float sIn[2][NTH * RSTRIDE];

    {
        // sWX: 3 x-gate products
        for (int idx = threadIdx.x; idx < EE * 32; idx += NTH){
            int i = idx >> 5, j = idx & 31;
            float v = 0.0f;
            if (j < 30){
                int m = j / 10, jj = j % 10;
                const float* a  = (m==0) ? Wi_r : (m==1) ? Wi_z : Wi_h;
                const float* b2 = (m==0) ? Ws_r : (m==1) ? Ws_z : Wt_h;
                #pragma unroll
                for (int k = 0; k < EE; k++) v = fmaf(a[i*EE + k], b2[k*EE + jj], v);
            }
            sWX[i][j] = v;
        }
        // sWH: 2 h-gate products
        for (int idx = threadIdx.x; idx < EE * 24; idx += NTH){
            int i = idx / 24, j = idx % 24;
            float v = 0.0f;
            if (j < 20){
                int m = j / 10, jj = j % 10;
                const float* a  = (m==0) ? Wh_r : Wh_z;
                const float* b2 = (m==0) ? Ws_r : Ws_z;
                #pragma unroll
                for (int k = 0; k < EE; k++) v = fmaf(a[i*EE + k], b2[k*EE + jj], v);
            }
            sWH[i][j] = v;
        }
        // sWG: candidate h-product
        for (int idx = threadIdx.x; idx < EE * 16; idx += NTH){
            int i = idx >> 4, j = idx & 15;
            float v = 0.0f;
            if (j < EE){
                #pragma unroll
                for (int k = 0; k < EE; k++) v = fmaf(Wh_h[i*EE + k], Wt_h[k*EE + j], v);
            }
            sWG[i][j] = v;
        }
        for (int idx = threadIdx.x; idx < 48; idx += NTH){
            int g = idx >> 4, j = idx & 15;
            float v = 0.0f;
            if (j < EE){
                const float* bi = (g==0) ? bi_r : (g==1) ? bi_z : bi_h;
                const float* bs = (g==0) ? bs_r : (g==1) ? bs_z : bt_h;
                const float* Wg = (g==0) ? Ws_r : (g==1) ? Ws_z : Wt_h;
                v = bs[j];
                #pragma unroll
                for (int k = 0; k < EE; k++) v = fmaf(bi[k], Wg[k*EE + j], v);
            }
            sB[g][j] = v;
        }
        if (threadIdx.x < 16) sH0[threadIdx.x] = (threadIdx.x < EE) ? h0[threadIdx.x] : 0.0f;
    }

    const int tid = threadIdx.x;
    const long b0 = (long)blockIdx.x * NTH;

    // Cooperative staging directly from [B][T][E]: NTH batches x 5 float2 per array.
    long goff[5]; int soff[5];
    #pragma unroll
    for (int k = 0; k < 5; k++){
        int idx = tid + NTH*k;
        int bb = idx / 5, pp = idx % 5;
        goff[k] = (b0 + bb) * (long)(TT*EE) + pp*2;
        soff[k] = bb * RSTRIDE + pp*2;
    }

    float2 fx[5], fa[5];
    #pragma unroll
    for (int k = 0; k < 5; k++){
        fx[k] = *(const float2*)(X   + goff[k]);
        fa[k] = *(const float2*)(Aat + goff[k]);
    }
    #pragma unroll
    for (int k = 0; k < 5; k++){
        *(float2*)&sIn[0][soff[k]]      = fx[k];
        *(float2*)&sIn[0][soff[k] + 10] = fa[k];
    }
    __syncthreads();

    float h[EE];
    #pragma unroll
    for (int j = 0; j < EE; j++) h[j] = sH0[j];

    #pragma unroll 1
    for (int t = 0; t < TT; t++){
        if (t + 1 < TT){
            #pragma unroll
            for (int k = 0; k < 5; k++){
                fx[k] = *(const float2*)(X   + goff[k] + (t+1)*EE);
                fa[k] = *(const float2*)(Aat + goff[k] + (t+1)*EE);
            }
        }

        const float* my = &sIn[t & 1][tid * RSTRIDE];
        float x[EE];
        #pragma unroll
        for (int p = 0; p < 5; p++){
            float2 v = *(const float2*)(my + 2*p);
            x[2*p] = v.x; x[2*p+1] = v.y;
        }

        u64 accR[5], accZ[5], accH[5];
        #pragma unroll
        for (int p = 0; p < 5; p++){
            accR[p] = *(const u64*)&sB[0][2*p];
            accZ[p] = *(const u64*)&sB[1][2*p];
            accH[p] = *(const u64*)&sB[2][2*p];
        }

        // x contributions: one packed 32-float row feeds all three gates (8 LDS.128)
        #pragma unroll
        for (int i = 0; i < EE; i++){
            u64 sx = splat2(x[i]);
            const ulonglong2* w = (const ulonglong2*)&sWX[i][0];
            ulonglong2 w0 = w[0], w1 = w[1], w2 = w[2], w3 = w[3];
            accR[0] = ffma2(sx, w0.x, accR[0]);
            accR[1] = ffma2(sx, w0.y, accR[1]);
            accR[2] = ffma2(sx, w1.x, accR[2]);
            accR[3] = ffma2(sx, w1.y, accR[3]);
            accR[4] = ffma2(sx, w2.x, accR[4]);
            accZ[0] = ffma2(sx, w2.y, accZ[0]);
            accZ[1] = ffma2(sx, w3.x, accZ[1]);
            accZ[2] = ffma2(sx, w3.y, accZ[2]);
            ulonglong2 w4 = w[4], w5 = w[5], w6 = w[6], w7 = w[7];
            accZ[3] = ffma2(sx, w4.x, accZ[3]);
            accZ[4] = ffma2(sx, w4.y, accZ[4]);
            accH[0] = ffma2(sx, w5.x, accH[0]);
            accH[1] = ffma2(sx, w5.y, accH[1]);
            accH[2] = ffma2(sx, w6.x, accH[2]);
            accH[3] = ffma2(sx, w6.y, accH[3]);
            accH[4] = ffma2(sx, w7.x, accH[4]);
        }
        // h contributions: one packed 24-float row feeds r and z (5 LDS.128)
        #pragma unroll
        for (int i = 0; i < EE; i++){
            u64 sh = splat2(h[i]);
            const ulonglong2* w = (const ulonglong2*)&sWH[i][0];
            ulonglong2 w0 = w[0], w1 = w[1];
            u64 w2x = ((const u64*)&sWH[i][0])[4];   // floats 8,9
            accR[0] = ffma2(sh, w0.x, accR[0]);
            accR[1] = ffma2(sh, w0.y, accR[1]);
            accR[2] = ffma2(sh, w1.x, accR[2]);
            accR[3] = ffma2(sh, w1.y, accR[3]);
            accR[4] = ffma2(sh, w2x,  accR[4]);
            ulonglong2 w2 = ((const ulonglong2*)&sWH[i][0])[2];  // floats 8..11 (8,9 | 10,11)
            ulonglong2 w3 = w[3], w4 = w[4];
            accZ[0] = ffma2(sh, w2.y, accZ[0]);
            accZ[1] = ffma2(sh, w3.x, accZ[1]);
            accZ[2] = ffma2(sh, w3.y, accZ[2]);
            accZ[3] = ffma2(sh, w4.x, accZ[3]);
            accZ[4] = ffma2(sh, w4.y, accZ[4]);
        }

        float r[EE], g[EE];
        #pragma unroll
        for (int p = 0; p < 5; p++){
            float r0, r1; unpack2(accR[p], r0, r1);
            r[2*p]   = sigmoidf_fast(r0);
            r[2*p+1] = sigmoidf_fast(r1);
            float z0, z1; unpack2(accZ[p], z0, z1);
            g[2*p]   = h[2*p]   * sigmoidf_fast(z0);
            g[2*p+1] = h[2*p+1] * sigmoidf_fast(z1);
        }

        // (h*z) contribution to candidate (3 LDS per row)
        #pragma unroll
        for (int i = 0; i < EE; i++){
            u64 sg = splat2(g[i]);
            const ulonglong2* w = (const ulonglong2*)&sWG[i][0];
            ulonglong2 w0 = w[0], w1 = w[1];
            u64 w4 = ((const u64*)&sWG[i][0])[4];
            accH[0] = ffma2(sg, w0.x, accH[0]);
            accH[1] = ffma2(sg, w0.y, accH[1]);
            accH[2] = ffma2(sg, w1.x, accH[2]);
            accH[3] = ffma2(sg, w1.y, accH[3]);
            accH[4] = ffma2(sg, w4,   accH[4]);
        }

        #pragma unroll
        for (int p = 0; p < 5; p++){
            float c0, c1; unpack2(accH[p], c0, c1);
            float hc0 = tanhf_fast(c0);
            float hc1 = tanhf_fast(c1);
            float2 av = *(const float2*)(my + 10 + 2*p);
            float Ra0 = av.x * r[2*p];
            float Ra1 = av.y * r[2*p+1];
            h[2*p]   = h[2*p]   + Ra0 * (hc0 - h[2*p]);
            h[2*p+1] = h[2*p+1] + Ra1 * (hc1 - h[2*p+1]);
        }

        if (t + 1 < TT){
            float* buf = sIn[(t + 1) & 1];
            #pragma unroll
            for (int k = 0; k < 5; k++){
                *(float2*)&buf[soff[k]]      = fx[k];
                *(float2*)&buf[soff[k] + 10] = fa[k];
            }
        }
        __syncthreads();
    }

    long b = b0 + tid;
    #pragma unroll
    for (int p = 0; p < 5; p++){
        float2 o; o.x = h[2*p]; o.y = h[2*p+1];
        *(float2*)(out + b*EE + 2*p) = o;
    }
}

extern "C" void kernel_launch(void* const* d_in, const int* in_sizes, int n_in,
                              void* d_out, int out_size)
{
    const float* X   = (const float*)d_in[0];
    const float* Aat = (const float*)d_in[1];
    const float* h0  = (const float*)d_in[2];

    augru_kernel<<<BB / NTH, NTH>>>(
        X, Aat, h0,
        (const float*)d_in[3],  (const float*)d_in[4],  (const float*)d_in[5],
        (const float*)d_in[6],  (const float*)d_in[7],
        (const float*)d_in[8],  (const float*)d_in[9],  (const float*)d_in[10],
        (const float*)d_in[11], (const float*)d_in[12],
        (const float*)d_in[13], (const float*)d_in[14], (const float*)d_in[15],
        (const float*)d_in[16], (const float*)d_in[17],
        (float*)d_out);
}